// round 15
// baseline (speedup 1.0000x reference)
#include <cuda_runtime.h>
#include <cuda_fp16.h>
#include <cstdint>

#define NB 4
#define CIN 64
#define HH 128
#define WW 128
#define COUT 128
#define NTAP 10            // 9 deform taps + 1 center-correction tap
#define NOFF 18

// ---- scratch (no allocations allowed) ----
__device__ __half g_xh[NB * HH * WW * CIN];             // 8.4 MB, NHWC fp16
__device__ float g_toff[NB * NOFF * HH * WW];           // 4.7 MB, NCHW
__device__ __half g_Ah[NTAP * COUT * 64];               // fused GEMM A (fp16): [tap][o][c]
__device__ __half g_Aoffh[32 * 576];                    // offset-conv A (fp16): [o(32)][k]

// ============================================================
// helpers
// ============================================================
__device__ __forceinline__ void mma_fp16(float* c, const uint32_t* a, const uint32_t* b) {
    asm volatile(
        "mma.sync.aligned.m16n8k16.row.col.f32.f16.f16.f32 "
        "{%0,%1,%2,%3}, {%4,%5,%6,%7}, {%8,%9}, {%0,%1,%2,%3};"
        : "+f"(c[0]), "+f"(c[1]), "+f"(c[2]), "+f"(c[3])
        : "r"(a[0]), "r"(a[1]), "r"(a[2]), "r"(a[3]), "r"(b[0]), "r"(b[1]));
}
__device__ __forceinline__ void ldsm_x4(uint32_t addr, uint32_t* r) {
    asm volatile("ldmatrix.sync.aligned.m8n8.x4.shared.b16 {%0,%1,%2,%3}, [%4];"
                 : "=r"(r[0]), "=r"(r[1]), "=r"(r[2]), "=r"(r[3]) : "r"(addr));
}
__device__ __forceinline__ uint32_t smem_u32(const void* p) {
    uint32_t a;
    asm("{ .reg .u64 t; cvta.to.shared.u64 t, %1; cvt.u32.u64 %0, t; }" : "=r"(a) : "l"(p));
    return a;
}
__device__ __forceinline__ void cp_async16(uint32_t dst, const void* src) {
    asm volatile("cp.async.cg.shared.global [%0], [%1], 16;" :: "r"(dst), "l"(src) : "memory");
}
__device__ __forceinline__ void cp_commit() {
    asm volatile("cp.async.commit_group;" ::: "memory");
}
__device__ __forceinline__ void cp_wait0() {
    asm volatile("cp.async.wait_group 0;" ::: "memory");
}
// fp16x2 bilinear combine of 8 channels (4 half2 lanes)
__device__ __forceinline__ uint4 comb8(uint4 q00, uint4 q01, uint4 q10, uint4 q11,
                                       __half2 w00, __half2 w01, __half2 w10, __half2 w11) {
    const __half2* a = (const __half2*)&q00;
    const __half2* b = (const __half2*)&q01;
    const __half2* c = (const __half2*)&q10;
    const __half2* d = (const __half2*)&q11;
    uint4 r;
    __half2* rr = (__half2*)&r;
    #pragma unroll
    for (int k = 0; k < 4; ++k) {
        __half2 s = __hmul2(a[k], w00);
        s = __hfma2(b[k], w01, s);
        s = __hfma2(c[k], w10, s);
        s = __hfma2(d[k], w11, s);
        rr[k] = s;
    }
    return r;
}

// ============================================================
// Transpose (NCHW -> NHWC fp16) + fused weight prep (R14 proven).
// ============================================================
__global__ void transpose_prep_kernel(const float* __restrict__ x,
                                      const float* __restrict__ w_off,
                                      const float* __restrict__ w_deform,
                                      const float* __restrict__ w_pw) {
    __shared__ float tile[CIN][33];
    int b = blockIdx.x;
    int wt = b & 3;
    int h  = (b >> 2) & 127;
    int n  = b >> 9;
    int w0 = wt * 32;

    // phase 1: issue all 8 loads
    float v[8];
    #pragma unroll
    for (int k = 0; k < 8; ++k) {
        int i = threadIdx.x + k * 256;
        int c = i >> 5, w = i & 31;
        v[k] = x[((n * CIN + c) * HH + h) * WW + w0 + w];
    }

    // ---- prep work (independent; overlaps load latency) ----
    int gtid = blockIdx.x * 256 + threadIdx.x;
    int gstride = gridDim.x * 256;
    for (int i = gtid; i < NTAP * CIN * COUT; i += gstride) {
        int o = i & 127;
        int k = i >> 7;
        int p = k >> 6;
        int c = k & 63;
        float acc = 0.f;
        if (p < 9) {
            #pragma unroll
            for (int d = 0; d < 4; ++d)
                acc += w_pw[o * 256 + c * 4 + d] * w_deform[(c * 4 + d) * 9 + p];
        } else {
            #pragma unroll
            for (int d = 0; d < 4; ++d) {
                float ws = 0.f;
                #pragma unroll
                for (int pp = 0; pp < 9; ++pp) ws += w_deform[(c * 4 + d) * 9 + pp];
                acc -= w_pw[o * 256 + c * 4 + d] * ws;
            }
        }
        g_Ah[p * 8192 + o * 64 + c] = __float2half_rn(acc);
    }
    for (int i = gtid; i < 32 * 576; i += gstride) {
        int k = i % 576;
        int o = i / 576;
        int t = k >> 6;
        int c = k & 63;
        float vv = 0.f;
        if (o < NOFF) {
            const float* wp = w_off + (o * CIN + c) * 9;
            vv = wp[t];
            if (t == 4) {
                float s = 0.f;
                #pragma unroll
                for (int tt = 0; tt < 9; ++tt) s += wp[tt];
                vv -= s;
            }
        }
        g_Aoffh[o * 576 + k] = __float2half_rn(vv);
    }

    // phase 2: store staged values
    #pragma unroll
    for (int k = 0; k < 8; ++k) {
        int i = threadIdx.x + k * 256;
        int c = i >> 5, w = i & 31;
        tile[c][w] = v[k];
    }
    __syncthreads();
    for (int i = threadIdx.x; i < 32 * 32; i += 256) {
        int w = i >> 5, cp = i & 31;
        __half2 hv = __float22half2_rn(make_float2(tile[2 * cp][w], tile[2 * cp + 1][w]));
        *(__half2*)&g_xh[((n * HH + h) * WW + w0 + w) * CIN + 2 * cp] = hv;
    }
}

// ============================================================
// Offset conv as single-pass fp16 tensor-core GEMM (proven form).
// ============================================================
#define XROW 72
#define XPIX 130
#define XPLANE (3 * XPIX * XROW)
#define AOP 584
#define OFF_SM_X 0
#define OFF_SM_A (XPLANE * 2)
#define OFF_SM_TOTAL (OFF_SM_A + 32 * AOP * 2)

__global__ void __launch_bounds__(512, 1) off_mma(const float* __restrict__ b_off) {
    extern __shared__ char sm[];
    __half* Xs = (__half*)(sm + OFF_SM_X);
    __half* Aw = (__half*)(sm + OFF_SM_A);

    int tid = threadIdx.x, wid = tid >> 5, lid = tid & 31;
    int g = lid >> 2, tq = lid & 3;
    int n = blockIdx.x >> 7, h = blockIdx.x & 127;
    int nw = wid * 8;

    for (int j = tid; j < 2304; j += 512) {
        int o = j / 72, seg = j % 72;
        *(uint4*)&Aw[o * AOP + seg * 8] = *(const uint4*)&g_Aoffh[o * 576 + seg * 8];
    }

    const __half* xb = g_xh + (size_t)n * (HH * WW * CIN);
    for (int e = tid; e < 3120; e += 512) {
        int r = e / 1040, rem = e % 1040;
        int p = rem >> 3, seg = rem & 7;
        int c0 = seg * 8;
        int row = h - 1 + r, w = p - 1;
        uint4 v = make_uint4(0, 0, 0, 0);
        if ((unsigned)row < (unsigned)HH && (unsigned)w < (unsigned)WW)
            v = *(const uint4*)&xb[(row * WW + w) * CIN + c0];
        *(uint4*)&Xs[r * (XPIX * XROW) + p * XROW + c0] = v;
    }
    __syncthreads();

    float acc[2][4];
    #pragma unroll
    for (int mi = 0; mi < 2; ++mi)
        #pragma unroll
        for (int r = 0; r < 4; ++r) acc[mi][r] = 0.f;

    #pragma unroll
    for (int t = 0; t < 9; ++t) {
        int ky = t / 3, kx = t % 3;
        #pragma unroll
        for (int ks = 0; ks < 4; ++ks) {
            int k0 = ks * 16;
            uint32_t a[2][4], b[2];
            #pragma unroll
            for (int mi = 0; mi < 2; ++mi) {
                const __half* ap = Aw + (mi * 16 + g) * AOP + t * 64 + k0 + 2 * tq;
                a[mi][0] = *(const uint32_t*)(ap);
                a[mi][1] = *(const uint32_t*)(ap + 8 * AOP);
                a[mi][2] = *(const uint32_t*)(ap + 8);
                a[mi][3] = *(const uint32_t*)(ap + 8 * AOP + 8);
            }
            const __half* bp = Xs + ky * (XPIX * XROW) + (nw + g + kx) * XROW + k0 + 2 * tq;
            b[0] = *(const uint32_t*)(bp);
            b[1] = *(const uint32_t*)(bp + 8);
            #pragma unroll
            for (int mi = 0; mi < 2; ++mi)
                mma_fp16(acc[mi], a[mi], b);
        }
    }

    int pix = nw + 2 * tq;
    #pragma unroll
    for (int mi = 0; mi < 2; ++mi) {
        int oa = mi * 16 + g;
        int ob = oa + 8;
        if (oa < NOFF) {
            float bb = __ldg(&b_off[oa]);
            *(float2*)&g_toff[((n * NOFF + oa) * HH + h) * WW + pix] =
                make_float2(acc[mi][0] + bb, acc[mi][1] + bb);
        }
        if (ob < NOFF) {
            float bb = __ldg(&b_off[ob]);
            *(float2*)&g_toff[((n * NOFF + ob) * HH + h) * WW + pix] =
                make_float2(acc[mi][2] + bb, acc[mi][3] + bb);
        }
    }
}

// ============================================================
// Fused deform-sample + fp16 GEMM (R13 body verbatim, proven 79.3us).
// 256 threads, M=128 x N=64, 73.7KB smem -> 3 CTAs/SM.
// ============================================================
#define PADK 72
#define NPIX 64
#define BTILE (NPIX * PADK)                  // 4608 halfs = 9216 B per buf
#define SM_PAR 0                             // sWh 9216 + sO 9216 = 18432 B
#define SM_A 18432                           // 2 x 18432 B
#define SM_B (18432 + 36864)                 // 2 x 9216 B
#define SM_TOTAL (SM_B + 18432)              // 73728 B

__global__ void __launch_bounds__(256, 3) fused_mma(float* __restrict__ out) {
    extern __shared__ char sm[];
    __half2* sWh = (__half2*)(sm + SM_PAR);             // [4][576]
    int*     sO  = (int*)(sm + SM_PAR + 4 * 576 * 4);   // [4][576]
    __half* Bs = (__half*)(sm + SM_B);
    uint32_t smbA = smem_u32(sm + SM_A);
    uint32_t smbB = smem_u32(sm + SM_B);

    int tid = threadIdx.x, wid = tid >> 5, lid = tid & 31;
    int n  = blockIdx.x >> 8;
    int h  = (blockIdx.x >> 1) & 127;
    int w0 = (blockIdx.x & 1) * NPIX;
    int g = lid >> 2, tq = lid & 3;
    int m0 = (wid & 3) * 32;
    int n0 = (wid >> 2) * 32;

    uint32_t aBase = (uint32_t)(((m0 + (lid & 15)) * PADK + ((lid >> 4) << 3)) * 2);
    uint32_t bBase = (uint32_t)(((n0 + (lid & 7) + ((lid >> 4) << 3)) * PADK
                                 + (((lid >> 3) & 1) << 3)) * 2);

    // ---- bilinear params per (tap, pixel): 9*64 = 576 entries ----
    for (int i = tid; i < 9 * NPIX; i += 256) {
        int p = i >> 6, pix = i & 63;
        int w = w0 + pix;
        float dy = g_toff[((n * NOFF + 2 * p    ) * HH + h) * WW + w];
        float dx = g_toff[((n * NOFF + 2 * p + 1) * HH + h) * WW + w];
        float py = dy + (float)(h - 1 + p / 3);
        float px = dx + (float)(w - 1 + p % 3);
        float y0f = floorf(py), x0f = floorf(px);
        int y0 = (int)y0f, x0 = (int)x0f;
        float wy1 = py - y0f, wx1 = px - x0f;
        float wy0 = 1.f - wy1, wx0 = 1.f - wx1;
        bool vy0 = (unsigned)y0 < (unsigned)HH, vy1 = (unsigned)(y0 + 1) < (unsigned)HH;
        bool vx0 = (unsigned)x0 < (unsigned)WW, vx1 = (unsigned)(x0 + 1) < (unsigned)WW;
        int cy0 = min(max(y0, 0), HH - 1), cy1 = min(max(y0 + 1, 0), HH - 1);
        int cx0 = min(max(x0, 0), WW - 1), cx1 = min(max(x0 + 1, 0), WW - 1);
        float f00 = (vy0 && vx0) ? wy0 * wx0 : 0.f;
        float f01 = (vy0 && vx1) ? wy0 * wx1 : 0.f;
        float f10 = (vy1 && vx0) ? wy1 * wx0 : 0.f;
        float f11 = (vy1 && vx1) ? wy1 * wx1 : 0.f;
        sWh[0 * 576 + i] = __half2half2(__float2half_rn(f00));
        sWh[1 * 576 + i] = __half2half2(__float2half_rn(f01));
        sWh[2 * 576 + i] = __half2half2(__float2half_rn(f10));
        sWh[3 * 576 + i] = __half2half2(__float2half_rn(f11));
        sO[0 * 576 + i] = (cy0 * WW + cx0) * CIN;
        sO[1 * 576 + i] = (cy0 * WW + cx1) * CIN;
        sO[2 * 576 + i] = (cy1 * WW + cx0) * CIN;
        sO[3 * 576 + i] = (cy1 * WW + cx1) * CIN;
    }

    const __half* xb = g_xh + (size_t)n * (HH * WW * CIN);

    // ---- prologue: A(0) via cp.async into buf 0 ----
    #pragma unroll
    for (int m = 0; m < 4; ++m) {
        int j = tid + 256 * m;
        int row = j >> 3, seg = j & 7;
        cp_async16(smbA + (uint32_t)(row * 144 + seg * 16), g_Ah + j * 8);
    }
    cp_commit();
    __syncthreads();   // params visible

    // ---- prologue: B(0) gathered inline into buf 0 (tap 0) ----
    #pragma unroll
    for (int b = 0; b < 2; ++b) {
        int j = tid + 256 * b;
        int pix = j >> 3, c0 = (j & 7) * 8;
        int i = pix;   // tap 0
        uint4 q00 = *(const uint4*)&xb[sO[i] + c0];
        uint4 q01 = *(const uint4*)&xb[sO[576 + i] + c0];
        uint4 q10 = *(const uint4*)&xb[sO[2 * 576 + i] + c0];
        uint4 q11 = *(const uint4*)&xb[sO[3 * 576 + i] + c0];
        *(uint4*)&Bs[pix * PADK + c0] =
            comb8(q00, q01, q10, q11, sWh[i], sWh[576 + i], sWh[2 * 576 + i], sWh[3 * 576 + i]);
    }

    float acc[2][4][4];
    #pragma unroll
    for (int mi = 0; mi < 2; ++mi)
        #pragma unroll
        for (int nj = 0; nj < 4; ++nj)
            #pragma unroll
            for (int r = 0; r < 4; ++r) acc[mi][nj][r] = 0.f;

    for (int t = 0; t < NTAP; ++t) {
        cp_wait0();
        __syncthreads();   // single barrier per tap: A(t), B(t) ready
        bool pf = (t < 9);
        bool center = (t + 1 == 9);

        uint32_t aBuf = smbA + (uint32_t)((t & 1) * 18432) + aBase;
        uint32_t bBuf = smbB + (uint32_t)((t & 1) * 9216) + bBase;
        __half* Bnx = Bs + ((t + 1) & 1) * BTILE;

        uint4 q[2][4];
        int pix0 = tid >> 3, c00 = (tid & 7) * 8;
        int pix1 = pix0 + 32;

        // issue BOTH gather batches for tap t+1 immediately (max distance)
        if (pf) {
            if (center) {
                q[0][0] = *(const uint4*)&xb[(h * WW + w0 + pix0) * CIN + c00];
                q[1][0] = *(const uint4*)&xb[(h * WW + w0 + pix1) * CIN + c00];
            } else {
                int i0 = (t + 1) * NPIX + pix0;
                int i1 = (t + 1) * NPIX + pix1;
                q[0][0] = *(const uint4*)&xb[sO[i0] + c00];
                q[0][1] = *(const uint4*)&xb[sO[576 + i0] + c00];
                q[0][2] = *(const uint4*)&xb[sO[2 * 576 + i0] + c00];
                q[0][3] = *(const uint4*)&xb[sO[3 * 576 + i0] + c00];
                q[1][0] = *(const uint4*)&xb[sO[i1] + c00];
                q[1][1] = *(const uint4*)&xb[sO[576 + i1] + c00];
                q[1][2] = *(const uint4*)&xb[sO[2 * 576 + i1] + c00];
                q[1][3] = *(const uint4*)&xb[sO[3 * 576 + i1] + c00];
            }
        }

        // prefetch A(t+1)
        if (pf) {
            const __half* asrc = g_Ah + (t + 1) * 8192;
            uint32_t adst = smbA + (uint32_t)(((t + 1) & 1) * 18432);
            #pragma unroll
            for (int m = 0; m < 4; ++m) {
                int j = tid + 256 * m;
                int row = j >> 3, seg = j & 7;
                cp_async16(adst + (uint32_t)(row * 144 + seg * 16), asrc + j * 8);
            }
            cp_commit();
        }

        auto mma_step = [&](int sub) {
            uint32_t kOff = (uint32_t)(sub * 32);
            uint32_t a[2][4], bfr[2][4];
            #pragma unroll
            for (int mi = 0; mi < 2; ++mi)
                ldsm_x4(aBuf + (uint32_t)(mi * 16 * PADK * 2) + kOff, a[mi]);
            #pragma unroll
            for (int njp = 0; njp < 2; ++njp)
                ldsm_x4(bBuf + (uint32_t)(njp * 16 * PADK * 2) + kOff, bfr[njp]);
            #pragma unroll
            for (int mi = 0; mi < 2; ++mi)
                #pragma unroll
                for (int nj = 0; nj < 4; ++nj)
                    mma_fp16(acc[mi][nj], a[mi], bfr[nj >> 1] + (nj & 1) * 2);
        };

        mma_step(0);
        mma_step(1);
        mma_step(2);
        if (pf) {
            uint4 r;
            if (center) {
                r = q[0][0];
            } else {
                int i = (t + 1) * NPIX + pix0;
                r = comb8(q[0][0], q[0][1], q[0][2], q[0][3],
                          sWh[i], sWh[576 + i], sWh[2 * 576 + i], sWh[3 * 576 + i]);
            }
            *(uint4*)&Bnx[pix0 * PADK + c00] = r;
        }
        mma_step(3);
        if (pf) {
            uint4 r;
            if (center) {
                r = q[1][0];
            } else {
                int i = (t + 1) * NPIX + pix1;
                r = comb8(q[1][0], q[1][1], q[1][2], q[1][3],
                          sWh[i], sWh[576 + i], sWh[2 * 576 + i], sWh[3 * 576 + i]);
            }
            *(uint4*)&Bnx[pix1 * PADK + c00] = r;
        }
    }

    // ---- epilogue: direct stores, NCHW ----
    #pragma unroll
    for (int mi = 0; mi < 2; ++mi) {
        #pragma unroll
        for (int nj = 0; nj < 4; ++nj) {
            int o = m0 + mi * 16 + g;
            int pix = w0 + n0 + nj * 8 + 2 * tq;
            float* op = out + (((size_t)n * COUT + o) * HH + h) * WW + pix;
            *(float2*)op = make_float2(acc[mi][nj][0], acc[mi][nj][1]);
            *(float2*)(op + 8 * HH * WW) = make_float2(acc[mi][nj][2], acc[mi][nj][3]);
        }
    }
}

// ============================================================
extern "C" void kernel_launch(void* const* d_in, const int* in_sizes, int n_in,
                              void* d_out, int out_size) {
    const float* x        = (const float*)d_in[0];
    const float* w_off    = (const float*)d_in[1];
    const float* b_off    = (const float*)d_in[2];
    const float* w_deform = (const float*)d_in[3];
    const float* w_pw     = (const float*)d_in[4];
    float* out = (float*)d_out;

    cudaFuncSetAttribute(off_mma,
                         cudaFuncAttributeMaxDynamicSharedMemorySize, OFF_SM_TOTAL);
    cudaFuncSetAttribute(fused_mma,
                         cudaFuncAttributeMaxDynamicSharedMemorySize, SM_TOTAL);

    transpose_prep_kernel<<<2048, 256>>>(x, w_off, w_deform, w_pw);
    off_mma<<<NB * HH, 512, OFF_SM_TOTAL>>>(b_off);
    fused_mma<<<NB * HH * 2, 256, SM_TOTAL>>>(out);
}

// round 16
// speedup vs baseline: 1.0016x; 1.0016x over previous
#include <cuda_runtime.h>
#include <cuda_fp16.h>
#include <cstdint>

#define NB 4
#define CIN 64
#define HH 128
#define WW 128
#define COUT 128
#define NTAP 10            // 9 deform taps + 1 center-correction tap
#define NOFF 18

// ---- scratch (no allocations allowed) ----
__device__ __half g_xh[NB * HH * WW * CIN];             // 8.4 MB, NHWC fp16
__device__ float g_toff[NB * NOFF * HH * WW];           // 4.7 MB, NCHW
__device__ __half g_Ah[NTAP * COUT * 64];               // fused GEMM A (fp16): [tap][o][c]
__device__ __half g_Aoffh[32 * 576];                    // offset-conv A (fp16): [o(32)][k]

// ============================================================
// helpers
// ============================================================
__device__ __forceinline__ void mma_fp16(float* c, const uint32_t* a, const uint32_t* b) {
    asm volatile(
        "mma.sync.aligned.m16n8k16.row.col.f32.f16.f16.f32 "
        "{%0,%1,%2,%3}, {%4,%5,%6,%7}, {%8,%9}, {%0,%1,%2,%3};"
        : "+f"(c[0]), "+f"(c[1]), "+f"(c[2]), "+f"(c[3])
        : "r"(a[0]), "r"(a[1]), "r"(a[2]), "r"(a[3]), "r"(b[0]), "r"(b[1]));
}
__device__ __forceinline__ void ldsm_x4(uint32_t addr, uint32_t* r) {
    asm volatile("ldmatrix.sync.aligned.m8n8.x4.shared.b16 {%0,%1,%2,%3}, [%4];"
                 : "=r"(r[0]), "=r"(r[1]), "=r"(r[2]), "=r"(r[3]) : "r"(addr));
}
__device__ __forceinline__ uint32_t smem_u32(const void* p) {
    uint32_t a;
    asm("{ .reg .u64 t; cvta.to.shared.u64 t, %1; cvt.u32.u64 %0, t; }" : "=r"(a) : "l"(p));
    return a;
}
__device__ __forceinline__ void cp_async16(uint32_t dst, const void* src) {
    asm volatile("cp.async.cg.shared.global [%0], [%1], 16;" :: "r"(dst), "l"(src) : "memory");
}
__device__ __forceinline__ void cp_commit() {
    asm volatile("cp.async.commit_group;" ::: "memory");
}
__device__ __forceinline__ void cp_wait0() {
    asm volatile("cp.async.wait_group 0;" ::: "memory");
}
// fp16x2 bilinear combine of 8 channels (4 half2 lanes)
__device__ __forceinline__ uint4 comb8(uint4 q00, uint4 q01, uint4 q10, uint4 q11,
                                       __half2 w00, __half2 w01, __half2 w10, __half2 w11) {
    const __half2* a = (const __half2*)&q00;
    const __half2* b = (const __half2*)&q01;
    const __half2* c = (const __half2*)&q10;
    const __half2* d = (const __half2*)&q11;
    uint4 r;
    __half2* rr = (__half2*)&r;
    #pragma unroll
    for (int k = 0; k < 4; ++k) {
        __half2 s = __hmul2(a[k], w00);
        s = __hfma2(b[k], w01, s);
        s = __hfma2(c[k], w10, s);
        s = __hfma2(d[k], w11, s);
        rr[k] = s;
    }
    return r;
}

// ============================================================
// Transpose (NCHW -> NHWC fp16) + fused weight prep (R14 proven).
// ============================================================
__global__ void transpose_prep_kernel(const float* __restrict__ x,
                                      const float* __restrict__ w_off,
                                      const float* __restrict__ w_deform,
                                      const float* __restrict__ w_pw) {
    __shared__ float tile[CIN][33];
    int b = blockIdx.x;
    int wt = b & 3;
    int h  = (b >> 2) & 127;
    int n  = b >> 9;
    int w0 = wt * 32;

    // phase 1: issue all 8 loads
    float v[8];
    #pragma unroll
    for (int k = 0; k < 8; ++k) {
        int i = threadIdx.x + k * 256;
        int c = i >> 5, w = i & 31;
        v[k] = x[((n * CIN + c) * HH + h) * WW + w0 + w];
    }

    // ---- prep work (independent; overlaps load latency) ----
    int gtid = blockIdx.x * 256 + threadIdx.x;
    int gstride = gridDim.x * 256;
    for (int i = gtid; i < NTAP * CIN * COUT; i += gstride) {
        int o = i & 127;
        int k = i >> 7;
        int p = k >> 6;
        int c = k & 63;
        float acc = 0.f;
        if (p < 9) {
            #pragma unroll
            for (int d = 0; d < 4; ++d)
                acc += w_pw[o * 256 + c * 4 + d] * w_deform[(c * 4 + d) * 9 + p];
        } else {
            #pragma unroll
            for (int d = 0; d < 4; ++d) {
                float ws = 0.f;
                #pragma unroll
                for (int pp = 0; pp < 9; ++pp) ws += w_deform[(c * 4 + d) * 9 + pp];
                acc -= w_pw[o * 256 + c * 4 + d] * ws;
            }
        }
        g_Ah[p * 8192 + o * 64 + c] = __float2half_rn(acc);
    }
    for (int i = gtid; i < 32 * 576; i += gstride) {
        int k = i % 576;
        int o = i / 576;
        int t = k >> 6;
        int c = k & 63;
        float vv = 0.f;
        if (o < NOFF) {
            const float* wp = w_off + (o * CIN + c) * 9;
            vv = wp[t];
            if (t == 4) {
                float s = 0.f;
                #pragma unroll
                for (int tt = 0; tt < 9; ++tt) s += wp[tt];
                vv -= s;
            }
        }
        g_Aoffh[o * 576 + k] = __float2half_rn(vv);
    }

    // phase 2: store staged values
    #pragma unroll
    for (int k = 0; k < 8; ++k) {
        int i = threadIdx.x + k * 256;
        int c = i >> 5, w = i & 31;
        tile[c][w] = v[k];
    }
    __syncthreads();
    for (int i = threadIdx.x; i < 32 * 32; i += 256) {
        int w = i >> 5, cp = i & 31;
        __half2 hv = __float22half2_rn(make_float2(tile[2 * cp][w], tile[2 * cp + 1][w]));
        *(__half2*)&g_xh[((n * HH + h) * WW + w0 + w) * CIN + 2 * cp] = hv;
    }
}

// ============================================================
// Offset conv as single-pass fp16 tensor-core GEMM.
// R16: __launch_bounds__(512, 2) -> regs capped at 64 -> 2 CTAs/SM
// (smem 93.5KB x 2 = 187KB fits). 512 blocks: 3.5 waves -> 1.7 waves.
// ============================================================
#define XROW 72
#define XPIX 130
#define XPLANE (3 * XPIX * XROW)
#define AOP 584
#define OFF_SM_X 0
#define OFF_SM_A (XPLANE * 2)
#define OFF_SM_TOTAL (OFF_SM_A + 32 * AOP * 2)

__global__ void __launch_bounds__(512, 2) off_mma(const float* __restrict__ b_off) {
    extern __shared__ char sm[];
    __half* Xs = (__half*)(sm + OFF_SM_X);
    __half* Aw = (__half*)(sm + OFF_SM_A);

    int tid = threadIdx.x, wid = tid >> 5, lid = tid & 31;
    int g = lid >> 2, tq = lid & 3;
    int n = blockIdx.x >> 7, h = blockIdx.x & 127;
    int nw = wid * 8;

    for (int j = tid; j < 2304; j += 512) {
        int o = j / 72, seg = j % 72;
        *(uint4*)&Aw[o * AOP + seg * 8] = *(const uint4*)&g_Aoffh[o * 576 + seg * 8];
    }

    const __half* xb = g_xh + (size_t)n * (HH * WW * CIN);
    for (int e = tid; e < 3120; e += 512) {
        int r = e / 1040, rem = e % 1040;
        int p = rem >> 3, seg = rem & 7;
        int c0 = seg * 8;
        int row = h - 1 + r, w = p - 1;
        uint4 v = make_uint4(0, 0, 0, 0);
        if ((unsigned)row < (unsigned)HH && (unsigned)w < (unsigned)WW)
            v = *(const uint4*)&xb[(row * WW + w) * CIN + c0];
        *(uint4*)&Xs[r * (XPIX * XROW) + p * XROW + c0] = v;
    }
    __syncthreads();

    float acc[2][4];
    #pragma unroll
    for (int mi = 0; mi < 2; ++mi)
        #pragma unroll
        for (int r = 0; r < 4; ++r) acc[mi][r] = 0.f;

    #pragma unroll
    for (int t = 0; t < 9; ++t) {
        int ky = t / 3, kx = t % 3;
        #pragma unroll
        for (int ks = 0; ks < 4; ++ks) {
            int k0 = ks * 16;
            uint32_t a[2][4], b[2];
            #pragma unroll
            for (int mi = 0; mi < 2; ++mi) {
                const __half* ap = Aw + (mi * 16 + g) * AOP + t * 64 + k0 + 2 * tq;
                a[mi][0] = *(const uint32_t*)(ap);
                a[mi][1] = *(const uint32_t*)(ap + 8 * AOP);
                a[mi][2] = *(const uint32_t*)(ap + 8);
                a[mi][3] = *(const uint32_t*)(ap + 8 * AOP + 8);
            }
            const __half* bp = Xs + ky * (XPIX * XROW) + (nw + g + kx) * XROW + k0 + 2 * tq;
            b[0] = *(const uint32_t*)(bp);
            b[1] = *(const uint32_t*)(bp + 8);
            #pragma unroll
            for (int mi = 0; mi < 2; ++mi)
                mma_fp16(acc[mi], a[mi], b);
        }
    }

    int pix = nw + 2 * tq;
    #pragma unroll
    for (int mi = 0; mi < 2; ++mi) {
        int oa = mi * 16 + g;
        int ob = oa + 8;
        if (oa < NOFF) {
            float bb = __ldg(&b_off[oa]);
            *(float2*)&g_toff[((n * NOFF + oa) * HH + h) * WW + pix] =
                make_float2(acc[mi][0] + bb, acc[mi][1] + bb);
        }
        if (ob < NOFF) {
            float bb = __ldg(&b_off[ob]);
            *(float2*)&g_toff[((n * NOFF + ob) * HH + h) * WW + pix] =
                make_float2(acc[mi][2] + bb, acc[mi][3] + bb);
        }
    }
}

// ============================================================
// Fused deform-sample + fp16 GEMM (R13 body verbatim).
// 256 threads, M=128 x N=64, 73.7KB smem -> 3 CTAs/SM.
// ============================================================
#define PADK 72
#define NPIX 64
#define BTILE (NPIX * PADK)                  // 4608 halfs = 9216 B per buf
#define SM_PAR 0                             // sWh 9216 + sO 9216 = 18432 B
#define SM_A 18432                           // 2 x 18432 B
#define SM_B (18432 + 36864)                 // 2 x 9216 B
#define SM_TOTAL (SM_B + 18432)              // 73728 B

__global__ void __launch_bounds__(256, 3) fused_mma(float* __restrict__ out) {
    extern __shared__ char sm[];
    __half2* sWh = (__half2*)(sm + SM_PAR);             // [4][576]
    int*     sO  = (int*)(sm + SM_PAR + 4 * 576 * 4);   // [4][576]
    __half* Bs = (__half*)(sm + SM_B);
    uint32_t smbA = smem_u32(sm + SM_A);
    uint32_t smbB = smem_u32(sm + SM_B);

    int tid = threadIdx.x, wid = tid >> 5, lid = tid & 31;
    int n  = blockIdx.x >> 8;
    int h  = (blockIdx.x >> 1) & 127;
    int w0 = (blockIdx.x & 1) * NPIX;
    int g = lid >> 2, tq = lid & 3;
    int m0 = (wid & 3) * 32;
    int n0 = (wid >> 2) * 32;

    uint32_t aBase = (uint32_t)(((m0 + (lid & 15)) * PADK + ((lid >> 4) << 3)) * 2);
    uint32_t bBase = (uint32_t)(((n0 + (lid & 7) + ((lid >> 4) << 3)) * PADK
                                 + (((lid >> 3) & 1) << 3)) * 2);

    // ---- bilinear params per (tap, pixel): 9*64 = 576 entries ----
    for (int i = tid; i < 9 * NPIX; i += 256) {
        int p = i >> 6, pix = i & 63;
        int w = w0 + pix;
        float dy = g_toff[((n * NOFF + 2 * p    ) * HH + h) * WW + w];
        float dx = g_toff[((n * NOFF + 2 * p + 1) * HH + h) * WW + w];
        float py = dy + (float)(h - 1 + p / 3);
        float px = dx + (float)(w - 1 + p % 3);
        float y0f = floorf(py), x0f = floorf(px);
        int y0 = (int)y0f, x0 = (int)x0f;
        float wy1 = py - y0f, wx1 = px - x0f;
        float wy0 = 1.f - wy1, wx0 = 1.f - wx1;
        bool vy0 = (unsigned)y0 < (unsigned)HH, vy1 = (unsigned)(y0 + 1) < (unsigned)HH;
        bool vx0 = (unsigned)x0 < (unsigned)WW, vx1 = (unsigned)(x0 + 1) < (unsigned)WW;
        int cy0 = min(max(y0, 0), HH - 1), cy1 = min(max(y0 + 1, 0), HH - 1);
        int cx0 = min(max(x0, 0), WW - 1), cx1 = min(max(x0 + 1, 0), WW - 1);
        float f00 = (vy0 && vx0) ? wy0 * wx0 : 0.f;
        float f01 = (vy0 && vx1) ? wy0 * wx1 : 0.f;
        float f10 = (vy1 && vx0) ? wy1 * wx0 : 0.f;
        float f11 = (vy1 && vx1) ? wy1 * wx1 : 0.f;
        sWh[0 * 576 + i] = __half2half2(__float2half_rn(f00));
        sWh[1 * 576 + i] = __half2half2(__float2half_rn(f01));
        sWh[2 * 576 + i] = __half2half2(__float2half_rn(f10));
        sWh[3 * 576 + i] = __half2half2(__float2half_rn(f11));
        sO[0 * 576 + i] = (cy0 * WW + cx0) * CIN;
        sO[1 * 576 + i] = (cy0 * WW + cx1) * CIN;
        sO[2 * 576 + i] = (cy1 * WW + cx0) * CIN;
        sO[3 * 576 + i] = (cy1 * WW + cx1) * CIN;
    }

    const __half* xb = g_xh + (size_t)n * (HH * WW * CIN);

    // ---- prologue: A(0) via cp.async into buf 0 ----
    #pragma unroll
    for (int m = 0; m < 4; ++m) {
        int j = tid + 256 * m;
        int row = j >> 3, seg = j & 7;
        cp_async16(smbA + (uint32_t)(row * 144 + seg * 16), g_Ah + j * 8);
    }
    cp_commit();
    __syncthreads();   // params visible

    // ---- prologue: B(0) gathered inline into buf 0 (tap 0) ----
    #pragma unroll
    for (int b = 0; b < 2; ++b) {
        int j = tid + 256 * b;
        int pix = j >> 3, c0 = (j & 7) * 8;
        int i = pix;   // tap 0
        uint4 q00 = *(const uint4*)&xb[sO[i] + c0];
        uint4 q01 = *(const uint4*)&xb[sO[576 + i] + c0];
        uint4 q10 = *(const uint4*)&xb[sO[2 * 576 + i] + c0];
        uint4 q11 = *(const uint4*)&xb[sO[3 * 576 + i] + c0];
        *(uint4*)&Bs[pix * PADK + c0] =
            comb8(q00, q01, q10, q11, sWh[i], sWh[576 + i], sWh[2 * 576 + i], sWh[3 * 576 + i]);
    }

    float acc[2][4][4];
    #pragma unroll
    for (int mi = 0; mi < 2; ++mi)
        #pragma unroll
        for (int nj = 0; nj < 4; ++nj)
            #pragma unroll
            for (int r = 0; r < 4; ++r) acc[mi][nj][r] = 0.f;

    for (int t = 0; t < NTAP; ++t) {
        cp_wait0();
        __syncthreads();   // single barrier per tap: A(t), B(t) ready
        bool pf = (t < 9);
        bool center = (t + 1 == 9);

        uint32_t aBuf = smbA + (uint32_t)((t & 1) * 18432) + aBase;
        uint32_t bBuf = smbB + (uint32_t)((t & 1) * 9216) + bBase;
        __half* Bnx = Bs + ((t + 1) & 1) * BTILE;

        uint4 q[2][4];
        int pix0 = tid >> 3, c00 = (tid & 7) * 8;
        int pix1 = pix0 + 32;

        // issue BOTH gather batches for tap t+1 immediately (max distance)
        if (pf) {
            if (center) {
                q[0][0] = *(const uint4*)&xb[(h * WW + w0 + pix0) * CIN + c00];
                q[1][0] = *(const uint4*)&xb[(h * WW + w0 + pix1) * CIN + c00];
            } else {
                int i0 = (t + 1) * NPIX + pix0;
                int i1 = (t + 1) * NPIX + pix1;
                q[0][0] = *(const uint4*)&xb[sO[i0] + c00];
                q[0][1] = *(const uint4*)&xb[sO[576 + i0] + c00];
                q[0][2] = *(const uint4*)&xb[sO[2 * 576 + i0] + c00];
                q[0][3] = *(const uint4*)&xb[sO[3 * 576 + i0] + c00];
                q[1][0] = *(const uint4*)&xb[sO[i1] + c00];
                q[1][1] = *(const uint4*)&xb[sO[576 + i1] + c00];
                q[1][2] = *(const uint4*)&xb[sO[2 * 576 + i1] + c00];
                q[1][3] = *(const uint4*)&xb[sO[3 * 576 + i1] + c00];
            }
        }

        // prefetch A(t+1)
        if (pf) {
            const __half* asrc = g_Ah + (t + 1) * 8192;
            uint32_t adst = smbA + (uint32_t)(((t + 1) & 1) * 18432);
            #pragma unroll
            for (int m = 0; m < 4; ++m) {
                int j = tid + 256 * m;
                int row = j >> 3, seg = j & 7;
                cp_async16(adst + (uint32_t)(row * 144 + seg * 16), asrc + j * 8);
            }
            cp_commit();
        }

        auto mma_step = [&](int sub) {
            uint32_t kOff = (uint32_t)(sub * 32);
            uint32_t a[2][4], bfr[2][4];
            #pragma unroll
            for (int mi = 0; mi < 2; ++mi)
                ldsm_x4(aBuf + (uint32_t)(mi * 16 * PADK * 2) + kOff, a[mi]);
            #pragma unroll
            for (int njp = 0; njp < 2; ++njp)
                ldsm_x4(bBuf + (uint32_t)(njp * 16 * PADK * 2) + kOff, bfr[njp]);
            #pragma unroll
            for (int mi = 0; mi < 2; ++mi)
                #pragma unroll
                for (int nj = 0; nj < 4; ++nj)
                    mma_fp16(acc[mi][nj], a[mi], bfr[nj >> 1] + (nj & 1) * 2);
        };

        mma_step(0);
        mma_step(1);
        mma_step(2);
        if (pf) {
            uint4 r;
            if (center) {
                r = q[0][0];
            } else {
                int i = (t + 1) * NPIX + pix0;
                r = comb8(q[0][0], q[0][1], q[0][2], q[0][3],
                          sWh[i], sWh[576 + i], sWh[2 * 576 + i], sWh[3 * 576 + i]);
            }
            *(uint4*)&Bnx[pix0 * PADK + c00] = r;
        }
        mma_step(3);
        if (pf) {
            uint4 r;
            if (center) {
                r = q[1][0];
            } else {
                int i = (t + 1) * NPIX + pix1;
                r = comb8(q[1][0], q[1][1], q[1][2], q[1][3],
                          sWh[i], sWh[576 + i], sWh[2 * 576 + i], sWh[3 * 576 + i]);
            }
            *(uint4*)&Bnx[pix1 * PADK + c00] = r;
        }
    }

    // ---- epilogue: direct stores, NCHW ----
    #pragma unroll
    for (int mi = 0; mi < 2; ++mi) {
        #pragma unroll
        for (int nj = 0; nj < 4; ++nj) {
            int o = m0 + mi * 16 + g;
            int pix = w0 + n0 + nj * 8 + 2 * tq;
            float* op = out + (((size_t)n * COUT + o) * HH + h) * WW + pix;
            *(float2*)op = make_float2(acc[mi][nj][0], acc[mi][nj][1]);
            *(float2*)(op + 8 * HH * WW) = make_float2(acc[mi][nj][2], acc[mi][nj][3]);
        }
    }
}

// ============================================================
extern "C" void kernel_launch(void* const* d_in, const int* in_sizes, int n_in,
                              void* d_out, int out_size) {
    const float* x        = (const float*)d_in[0];
    const float* w_off    = (const float*)d_in[1];
    const float* b_off    = (const float*)d_in[2];
    const float* w_deform = (const float*)d_in[3];
    const float* w_pw     = (const float*)d_in[4];
    float* out = (float*)d_out;

    cudaFuncSetAttribute(off_mma,
                         cudaFuncAttributeMaxDynamicSharedMemorySize, OFF_SM_TOTAL);
    cudaFuncSetAttribute(fused_mma,
                         cudaFuncAttributeMaxDynamicSharedMemorySize, SM_TOTAL);

    transpose_prep_kernel<<<2048, 256>>>(x, w_off, w_deform, w_pw);
    off_mma<<<NB * HH, 512, OFF_SM_TOTAL>>>(b_off);
    fused_mma<<<NB * HH * 2, 256, SM_TOTAL>>>(out);
}

// round 17
// speedup vs baseline: 1.0082x; 1.0066x over previous
#include <cuda_runtime.h>
#include <cuda_fp16.h>
#include <cstdint>

#define NB 4
#define CIN 64
#define HH 128
#define WW 128
#define COUT 128
#define NTAP 10            // 9 deform taps + 1 center-correction tap
#define NOFF 18

// ---- scratch (no allocations allowed) ----
__device__ __half g_xh[NB * HH * WW * CIN];             // 8.4 MB, NHWC fp16
__device__ float g_toff[NB * NOFF * HH * WW];           // 4.7 MB, NCHW
__device__ __half g_Ah[NTAP * COUT * 64];               // fused GEMM A (fp16): [tap][o][c]
__device__ __half g_Aoffh[32 * 576];                    // offset-conv A (fp16): [o(32)][k]

// ============================================================
// helpers
// ============================================================
__device__ __forceinline__ void mma_fp16(float* c, const uint32_t* a, const uint32_t* b) {
    asm volatile(
        "mma.sync.aligned.m16n8k16.row.col.f32.f16.f16.f32 "
        "{%0,%1,%2,%3}, {%4,%5,%6,%7}, {%8,%9}, {%0,%1,%2,%3};"
        : "+f"(c[0]), "+f"(c[1]), "+f"(c[2]), "+f"(c[3])
        : "r"(a[0]), "r"(a[1]), "r"(a[2]), "r"(a[3]), "r"(b[0]), "r"(b[1]));
}
__device__ __forceinline__ void ldsm_x4(uint32_t addr, uint32_t* r) {
    asm volatile("ldmatrix.sync.aligned.m8n8.x4.shared.b16 {%0,%1,%2,%3}, [%4];"
                 : "=r"(r[0]), "=r"(r[1]), "=r"(r[2]), "=r"(r[3]) : "r"(addr));
}
__device__ __forceinline__ uint32_t smem_u32(const void* p) {
    uint32_t a;
    asm("{ .reg .u64 t; cvta.to.shared.u64 t, %1; cvt.u32.u64 %0, t; }" : "=r"(a) : "l"(p));
    return a;
}
__device__ __forceinline__ void cp_async16(uint32_t dst, const void* src) {
    asm volatile("cp.async.cg.shared.global [%0], [%1], 16;" :: "r"(dst), "l"(src) : "memory");
}
__device__ __forceinline__ void cp_commit() {
    asm volatile("cp.async.commit_group;" ::: "memory");
}
__device__ __forceinline__ void cp_wait0() {
    asm volatile("cp.async.wait_group 0;" ::: "memory");
}
// fp16x2 bilinear combine of 8 channels (4 half2 lanes)
__device__ __forceinline__ uint4 comb8(uint4 q00, uint4 q01, uint4 q10, uint4 q11,
                                       __half2 w00, __half2 w01, __half2 w10, __half2 w11) {
    const __half2* a = (const __half2*)&q00;
    const __half2* b = (const __half2*)&q01;
    const __half2* c = (const __half2*)&q10;
    const __half2* d = (const __half2*)&q11;
    uint4 r;
    __half2* rr = (__half2*)&r;
    #pragma unroll
    for (int k = 0; k < 4; ++k) {
        __half2 s = __hmul2(a[k], w00);
        s = __hfma2(b[k], w01, s);
        s = __hfma2(c[k], w10, s);
        s = __hfma2(d[k], w11, s);
        rr[k] = s;
    }
    return r;
}

// ============================================================
// Transpose (NCHW -> NHWC fp16) + fused weight prep.
// R17: phase-2 emits 16B coalesced stores (thread = pixel x 8-ch group).
// ============================================================
__global__ void transpose_prep_kernel(const float* __restrict__ x,
                                      const float* __restrict__ w_off,
                                      const float* __restrict__ w_deform,
                                      const float* __restrict__ w_pw) {
    __shared__ float tile[CIN][33];
    int b = blockIdx.x;
    int wt = b & 3;
    int h  = (b >> 2) & 127;
    int n  = b >> 9;
    int w0 = wt * 32;

    // phase 1: issue all 8 loads
    float v[8];
    #pragma unroll
    for (int k = 0; k < 8; ++k) {
        int i = threadIdx.x + k * 256;
        int c = i >> 5, w = i & 31;
        v[k] = x[((n * CIN + c) * HH + h) * WW + w0 + w];
    }

    // ---- prep work (independent; overlaps load latency) ----
    int gtid = blockIdx.x * 256 + threadIdx.x;
    int gstride = gridDim.x * 256;
    for (int i = gtid; i < NTAP * CIN * COUT; i += gstride) {
        int o = i & 127;
        int k = i >> 7;
        int p = k >> 6;
        int c = k & 63;
        float acc = 0.f;
        if (p < 9) {
            #pragma unroll
            for (int d = 0; d < 4; ++d)
                acc += w_pw[o * 256 + c * 4 + d] * w_deform[(c * 4 + d) * 9 + p];
        } else {
            #pragma unroll
            for (int d = 0; d < 4; ++d) {
                float ws = 0.f;
                #pragma unroll
                for (int pp = 0; pp < 9; ++pp) ws += w_deform[(c * 4 + d) * 9 + pp];
                acc -= w_pw[o * 256 + c * 4 + d] * ws;
            }
        }
        g_Ah[p * 8192 + o * 64 + c] = __float2half_rn(acc);
    }
    for (int i = gtid; i < 32 * 576; i += gstride) {
        int k = i % 576;
        int o = i / 576;
        int t = k >> 6;
        int c = k & 63;
        float vv = 0.f;
        if (o < NOFF) {
            const float* wp = w_off + (o * CIN + c) * 9;
            vv = wp[t];
            if (t == 4) {
                float s = 0.f;
                #pragma unroll
                for (int tt = 0; tt < 9; ++tt) s += wp[tt];
                vv -= s;
            }
        }
        g_Aoffh[o * 576 + k] = __float2half_rn(vv);
    }

    // phase 2: stage to smem, then 16B coalesced stores
    #pragma unroll
    for (int k = 0; k < 8; ++k) {
        int i = threadIdx.x + k * 256;
        int c = i >> 5, w = i & 31;
        tile[c][w] = v[k];
    }
    __syncthreads();
    {
        int w  = threadIdx.x >> 3;            // pixel within 32-col strip
        int c0 = (threadIdx.x & 7) * 8;       // 8-channel group
        uint4 pk;
        __half2* ph = (__half2*)&pk;
        #pragma unroll
        for (int j = 0; j < 4; ++j)
            ph[j] = __float22half2_rn(make_float2(tile[c0 + 2 * j][w], tile[c0 + 2 * j + 1][w]));
        *(uint4*)&g_xh[((n * HH + h) * WW + w0 + w) * CIN + c0] = pk;
    }
}

// ============================================================
// Offset conv as single-pass fp16 tensor-core GEMM.
// R17: __launch_bounds__(512, 2) -> 2 CTAs/SM (smem 93.5KB x 2 fits).
// ============================================================
#define XROW 72
#define XPIX 130
#define XPLANE (3 * XPIX * XROW)
#define AOP 584
#define OFF_SM_X 0
#define OFF_SM_A (XPLANE * 2)
#define OFF_SM_TOTAL (OFF_SM_A + 32 * AOP * 2)

__global__ void __launch_bounds__(512, 2) off_mma(const float* __restrict__ b_off) {
    extern __shared__ char sm[];
    __half* Xs = (__half*)(sm + OFF_SM_X);
    __half* Aw = (__half*)(sm + OFF_SM_A);

    int tid = threadIdx.x, wid = tid >> 5, lid = tid & 31;
    int g = lid >> 2, tq = lid & 3;
    int n = blockIdx.x >> 7, h = blockIdx.x & 127;
    int nw = wid * 8;

    for (int j = tid; j < 2304; j += 512) {
        int o = j / 72, seg = j % 72;
        *(uint4*)&Aw[o * AOP + seg * 8] = *(const uint4*)&g_Aoffh[o * 576 + seg * 8];
    }

    const __half* xb = g_xh + (size_t)n * (HH * WW * CIN);
    for (int e = tid; e < 3120; e += 512) {
        int r = e / 1040, rem = e % 1040;
        int p = rem >> 3, seg = rem & 7;
        int c0 = seg * 8;
        int row = h - 1 + r, w = p - 1;
        uint4 v = make_uint4(0, 0, 0, 0);
        if ((unsigned)row < (unsigned)HH && (unsigned)w < (unsigned)WW)
            v = *(const uint4*)&xb[(row * WW + w) * CIN + c0];
        *(uint4*)&Xs[r * (XPIX * XROW) + p * XROW + c0] = v;
    }
    __syncthreads();

    float acc[2][4];
    #pragma unroll
    for (int mi = 0; mi < 2; ++mi)
        #pragma unroll
        for (int r = 0; r < 4; ++r) acc[mi][r] = 0.f;

    #pragma unroll
    for (int t = 0; t < 9; ++t) {
        int ky = t / 3, kx = t % 3;
        #pragma unroll
        for (int ks = 0; ks < 4; ++ks) {
            int k0 = ks * 16;
            uint32_t a[2][4], b[2];
            #pragma unroll
            for (int mi = 0; mi < 2; ++mi) {
                const __half* ap = Aw + (mi * 16 + g) * AOP + t * 64 + k0 + 2 * tq;
                a[mi][0] = *(const uint32_t*)(ap);
                a[mi][1] = *(const uint32_t*)(ap + 8 * AOP);
                a[mi][2] = *(const uint32_t*)(ap + 8);
                a[mi][3] = *(const uint32_t*)(ap + 8 * AOP + 8);
            }
            const __half* bp = Xs + ky * (XPIX * XROW) + (nw + g + kx) * XROW + k0 + 2 * tq;
            b[0] = *(const uint32_t*)(bp);
            b[1] = *(const uint32_t*)(bp + 8);
            #pragma unroll
            for (int mi = 0; mi < 2; ++mi)
                mma_fp16(acc[mi], a[mi], b);
        }
    }

    int pix = nw + 2 * tq;
    #pragma unroll
    for (int mi = 0; mi < 2; ++mi) {
        int oa = mi * 16 + g;
        int ob = oa + 8;
        if (oa < NOFF) {
            float bb = __ldg(&b_off[oa]);
            *(float2*)&g_toff[((n * NOFF + oa) * HH + h) * WW + pix] =
                make_float2(acc[mi][0] + bb, acc[mi][1] + bb);
        }
        if (ob < NOFF) {
            float bb = __ldg(&b_off[ob]);
            *(float2*)&g_toff[((n * NOFF + ob) * HH + h) * WW + pix] =
                make_float2(acc[mi][2] + bb, acc[mi][3] + bb);
        }
    }
}

// ============================================================
// Fused deform-sample + fp16 GEMM (R14 body verbatim, best-measured).
// Packed params: ushort pixel idx + scalar half weights; 64.5KB smem.
// ============================================================
#define PADK 72
#define NPIX 64
#define BTILE (NPIX * PADK)                  // 4608 halfs = 9216 B per buf
#define SM_PAR 0                             // sWhs 4608 + sOp 4608 = 9216 B
#define SM_A 9216                            // 2 x 18432 B
#define SM_B (9216 + 36864)                  // 2 x 9216 B
#define SM_TOTAL (SM_B + 18432)              // 64512 B

__global__ void __launch_bounds__(256, 3) fused_mma(float* __restrict__ out) {
    extern __shared__ char sm[];
    __half*   sWhs = (__half*)(sm + SM_PAR);               // [4][576] scalar weights
    uint16_t* sOp  = (uint16_t*)(sm + SM_PAR + 4 * 576 * 2); // [4][576] pixel indices
    __half* Bs = (__half*)(sm + SM_B);
    uint32_t smbA = smem_u32(sm + SM_A);
    uint32_t smbB = smem_u32(sm + SM_B);

    int tid = threadIdx.x, wid = tid >> 5, lid = tid & 31;
    int n  = blockIdx.x >> 8;
    int h  = (blockIdx.x >> 1) & 127;
    int w0 = (blockIdx.x & 1) * NPIX;
    int g = lid >> 2, tq = lid & 3;
    int m0 = (wid & 3) * 32;
    int n0 = (wid >> 2) * 32;

    uint32_t aBase = (uint32_t)(((m0 + (lid & 15)) * PADK + ((lid >> 4) << 3)) * 2);
    uint32_t bBase = (uint32_t)(((n0 + (lid & 7) + ((lid >> 4) << 3)) * PADK
                                 + (((lid >> 3) & 1) << 3)) * 2);

    // ---- bilinear params per (tap, pixel): 9*64 = 576 entries ----
    for (int i = tid; i < 9 * NPIX; i += 256) {
        int p = i >> 6, pix = i & 63;
        int w = w0 + pix;
        float dy = g_toff[((n * NOFF + 2 * p    ) * HH + h) * WW + w];
        float dx = g_toff[((n * NOFF + 2 * p + 1) * HH + h) * WW + w];
        float py = dy + (float)(h - 1 + p / 3);
        float px = dx + (float)(w - 1 + p % 3);
        float y0f = floorf(py), x0f = floorf(px);
        int y0 = (int)y0f, x0 = (int)x0f;
        float wy1 = py - y0f, wx1 = px - x0f;
        float wy0 = 1.f - wy1, wx0 = 1.f - wx1;
        bool vy0 = (unsigned)y0 < (unsigned)HH, vy1 = (unsigned)(y0 + 1) < (unsigned)HH;
        bool vx0 = (unsigned)x0 < (unsigned)WW, vx1 = (unsigned)(x0 + 1) < (unsigned)WW;
        int cy0 = min(max(y0, 0), HH - 1), cy1 = min(max(y0 + 1, 0), HH - 1);
        int cx0 = min(max(x0, 0), WW - 1), cx1 = min(max(x0 + 1, 0), WW - 1);
        float f00 = (vy0 && vx0) ? wy0 * wx0 : 0.f;
        float f01 = (vy0 && vx1) ? wy0 * wx1 : 0.f;
        float f10 = (vy1 && vx0) ? wy1 * wx0 : 0.f;
        float f11 = (vy1 && vx1) ? wy1 * wx1 : 0.f;
        sWhs[0 * 576 + i] = __float2half_rn(f00);
        sWhs[1 * 576 + i] = __float2half_rn(f01);
        sWhs[2 * 576 + i] = __float2half_rn(f10);
        sWhs[3 * 576 + i] = __float2half_rn(f11);
        sOp[0 * 576 + i] = (uint16_t)(cy0 * WW + cx0);
        sOp[1 * 576 + i] = (uint16_t)(cy0 * WW + cx1);
        sOp[2 * 576 + i] = (uint16_t)(cy1 * WW + cx0);
        sOp[3 * 576 + i] = (uint16_t)(cy1 * WW + cx1);
    }

    const __half* xb = g_xh + (size_t)n * (HH * WW * CIN);

    // ---- prologue: A(0) via cp.async into buf 0 ----
    #pragma unroll
    for (int m = 0; m < 4; ++m) {
        int j = tid + 256 * m;
        int row = j >> 3, seg = j & 7;
        cp_async16(smbA + (uint32_t)(row * 144 + seg * 16), g_Ah + j * 8);
    }
    cp_commit();
    __syncthreads();   // params visible

    // ---- prologue: B(0) gathered inline into buf 0 (tap 0) ----
    #pragma unroll
    for (int b = 0; b < 2; ++b) {
        int j = tid + 256 * b;
        int pix = j >> 3, c0 = (j & 7) * 8;
        int i = pix;   // tap 0
        uint4 q00 = *(const uint4*)&xb[(int)sOp[i] * CIN + c0];
        uint4 q01 = *(const uint4*)&xb[(int)sOp[576 + i] * CIN + c0];
        uint4 q10 = *(const uint4*)&xb[(int)sOp[2 * 576 + i] * CIN + c0];
        uint4 q11 = *(const uint4*)&xb[(int)sOp[3 * 576 + i] * CIN + c0];
        *(uint4*)&Bs[pix * PADK + c0] =
            comb8(q00, q01, q10, q11,
                  __half2half2(sWhs[i]), __half2half2(sWhs[576 + i]),
                  __half2half2(sWhs[2 * 576 + i]), __half2half2(sWhs[3 * 576 + i]));
    }

    float acc[2][4][4];
    #pragma unroll
    for (int mi = 0; mi < 2; ++mi)
        #pragma unroll
        for (int nj = 0; nj < 4; ++nj)
            #pragma unroll
            for (int r = 0; r < 4; ++r) acc[mi][nj][r] = 0.f;

    for (int t = 0; t < NTAP; ++t) {
        cp_wait0();
        __syncthreads();   // single barrier per tap: A(t), B(t) ready
        bool pf = (t < 9);
        bool center = (t + 1 == 9);

        uint32_t aBuf = smbA + (uint32_t)((t & 1) * 18432) + aBase;
        uint32_t bBuf = smbB + (uint32_t)((t & 1) * 9216) + bBase;
        __half* Bnx = Bs + ((t + 1) & 1) * BTILE;

        uint4 q[2][4];
        int pix0 = tid >> 3, c00 = (tid & 7) * 8;
        int pix1 = pix0 + 32;

        // issue BOTH gather batches for tap t+1 immediately (max distance)
        if (pf) {
            if (center) {
                q[0][0] = *(const uint4*)&xb[(h * WW + w0 + pix0) * CIN + c00];
                q[1][0] = *(const uint4*)&xb[(h * WW + w0 + pix1) * CIN + c00];
            } else {
                int i0 = (t + 1) * NPIX + pix0;
                int i1 = (t + 1) * NPIX + pix1;
                q[0][0] = *(const uint4*)&xb[(int)sOp[i0] * CIN + c00];
                q[0][1] = *(const uint4*)&xb[(int)sOp[576 + i0] * CIN + c00];
                q[0][2] = *(const uint4*)&xb[(int)sOp[2 * 576 + i0] * CIN + c00];
                q[0][3] = *(const uint4*)&xb[(int)sOp[3 * 576 + i0] * CIN + c00];
                q[1][0] = *(const uint4*)&xb[(int)sOp[i1] * CIN + c00];
                q[1][1] = *(const uint4*)&xb[(int)sOp[576 + i1] * CIN + c00];
                q[1][2] = *(const uint4*)&xb[(int)sOp[2 * 576 + i1] * CIN + c00];
                q[1][3] = *(const uint4*)&xb[(int)sOp[3 * 576 + i1] * CIN + c00];
            }
        }

        // prefetch A(t+1)
        if (pf) {
            const __half* asrc = g_Ah + (t + 1) * 8192;
            uint32_t adst = smbA + (uint32_t)(((t + 1) & 1) * 18432);
            #pragma unroll
            for (int m = 0; m < 4; ++m) {
                int j = tid + 256 * m;
                int row = j >> 3, seg = j & 7;
                cp_async16(adst + (uint32_t)(row * 144 + seg * 16), asrc + j * 8);
            }
            cp_commit();
        }

        auto mma_step = [&](int sub) {
            uint32_t kOff = (uint32_t)(sub * 32);
            uint32_t a[2][4], bfr[2][4];
            #pragma unroll
            for (int mi = 0; mi < 2; ++mi)
                ldsm_x4(aBuf + (uint32_t)(mi * 16 * PADK * 2) + kOff, a[mi]);
            #pragma unroll
            for (int njp = 0; njp < 2; ++njp)
                ldsm_x4(bBuf + (uint32_t)(njp * 16 * PADK * 2) + kOff, bfr[njp]);
            #pragma unroll
            for (int mi = 0; mi < 2; ++mi)
                #pragma unroll
                for (int nj = 0; nj < 4; ++nj)
                    mma_fp16(acc[mi][nj], a[mi], bfr[nj >> 1] + (nj & 1) * 2);
        };

        mma_step(0);
        mma_step(1);
        mma_step(2);
        if (pf) {
            uint4 r;
            if (center) {
                r = q[0][0];
            } else {
                int i = (t + 1) * NPIX + pix0;
                r = comb8(q[0][0], q[0][1], q[0][2], q[0][3],
                          __half2half2(sWhs[i]), __half2half2(sWhs[576 + i]),
                          __half2half2(sWhs[2 * 576 + i]), __half2half2(sWhs[3 * 576 + i]));
            }
            *(uint4*)&Bnx[pix0 * PADK + c00] = r;
        }
        mma_step(3);
        if (pf) {
            uint4 r;
            if (center) {
                r = q[1][0];
            } else {
                int i = (t + 1) * NPIX + pix1;
                r = comb8(q[1][0], q[1][1], q[1][2], q[1][3],
                          __half2half2(sWhs[i]), __half2half2(sWhs[576 + i]),
                          __half2half2(sWhs[2 * 576 + i]), __half2half2(sWhs[3 * 576 + i]));
            }
            *(uint4*)&Bnx[pix1 * PADK + c00] = r;
        }
    }

    // ---- epilogue: direct stores, NCHW ----
    #pragma unroll
    for (int mi = 0; mi < 2; ++mi) {
        #pragma unroll
        for (int nj = 0; nj < 4; ++nj) {
            int o = m0 + mi * 16 + g;
            int pix = w0 + n0 + nj * 8 + 2 * tq;
            float* op = out + (((size_t)n * COUT + o) * HH + h) * WW + pix;
            *(float2*)op = make_float2(acc[mi][nj][0], acc[mi][nj][1]);
            *(float2*)(op + 8 * HH * WW) = make_float2(acc[mi][nj][2], acc[mi][nj][3]);
        }
    }
}

// ============================================================
extern "C" void kernel_launch(void* const* d_in, const int* in_sizes, int n_in,
                              void* d_out, int out_size) {
    const float* x        = (const float*)d_in[0];
    const float* w_off    = (const float*)d_in[1];
    const float* b_off    = (const float*)d_in[2];
    const float* w_deform = (const float*)d_in[3];
    const float* w_pw     = (const float*)d_in[4];
    float* out = (float*)d_out;

    cudaFuncSetAttribute(off_mma,
                         cudaFuncAttributeMaxDynamicSharedMemorySize, OFF_SM_TOTAL);
    cudaFuncSetAttribute(fused_mma,
                         cudaFuncAttributeMaxDynamicSharedMemorySize, SM_TOTAL);

    transpose_prep_kernel<<<2048, 256>>>(x, w_off, w_deform, w_pw);
    off_mma<<<NB * HH, 512, OFF_SM_TOTAL>>>(b_off);
    fused_mma<<<NB * HH * 2, 256, SM_TOTAL>>>(out);
}